// round 2
// baseline (speedup 1.0000x reference)
#include <cuda_runtime.h>
#include <cstdint>
#include <cstddef>

// Problem constants
#define Bsz   32
#define Tlen  1024
#define Hdim  512
#define G4    2048                 // 4*H
#define Mrows (Tlen * Bsz)         // 32768
#define NCTA  128                  // recurrent CTAs (co-resident, <=148 SMs)
#define RTHREADS 256

// ---------------- static device scratch (no allocations allowed) -------------
__device__ float g_G[(size_t)Mrows * G4];        // gate pre-activations [m][4H], m = t*B+b
__device__ float g_h1[(size_t)Mrows * Hdim];     // layer-0 outputs, [t*B+b][H]
__device__ float g_h2[(size_t)Mrows * Hdim];     // layer-1 outputs, [t*B+b][H]
__device__ float g_hkb[(size_t)Tlen * Hdim * Bsz]; // h in [t][k][b] layout for recurrence
__device__ int   g_cnt[2][Tlen];                 // per-step arrival counters (one per layer)

// ---------------- helpers ----------------------------------------------------
__device__ __forceinline__ float sigm_(float x) { return 1.0f / (1.0f + __expf(-x)); }
__device__ __forceinline__ float tanh_(float x) {
    float y;
    asm("tanh.approx.f32 %0, %1;" : "=f"(y) : "f"(x));
    return y;
}

// ---------------- counter reset (graph-replay safe) --------------------------
__global__ void zero_cnt_kernel() {
    int i = blockIdx.x * blockDim.x + threadIdx.x;
    if (i < 2 * Tlen) ((int*)g_cnt)[i] = 0;
}

// ---------------- SGEMM: C[m][n] = sum_k A[m][k]*W[n][k] + bias --------------
// A is K-contiguous per row (K = Hdim = 512). W row-major [N][K].
// amode 0: A row m maps to x[(m%B)*T + m/B][.]   (x is [B,T,H])
// amode 1: A row m maps to A[m][.]               (hseq is [T*B,H])
// cmode 0: C row m -> C[m*N]                     (G buffer, [T*B,4H])
// cmode 1: C row m -> C[((m%B)*T + m/B)*N]       (final out is [B,T,H])
__global__ __launch_bounds__(256, 2) void sgemm_nt(
    const float* __restrict__ A, const float* __restrict__ W,
    const float* __restrict__ b1, const float* __restrict__ b2,
    float* __restrict__ C, int N, int amode, int cmode)
{
    const int K = Hdim;
    __shared__ float As[16 * 132];
    __shared__ float Bs[16 * 132];

    const int tid = threadIdx.x;
    const int bm = blockIdx.y * 128;
    const int bn = blockIdx.x * 128;

    const int lrow = tid >> 2;          // 0..63
    const int lk   = (tid & 3) * 4;     // 0,4,8,12
    const int tx   = tid & 15;
    const int ty   = tid >> 4;

    size_t arow0, arow1;
    {
        int m0 = bm + lrow, m1 = m0 + 64;
        if (amode) {
            arow0 = (size_t)m0 * K;
            arow1 = (size_t)m1 * K;
        } else {
            arow0 = ((size_t)(m0 & 31) * Tlen + (size_t)(m0 >> 5)) * K;
            arow1 = ((size_t)(m1 & 31) * Tlen + (size_t)(m1 >> 5)) * K;
        }
    }
    const float* W0 = W + (size_t)(bn + lrow) * K;
    const float* W1 = W0 + (size_t)64 * K;

    float acc[8][8];
#pragma unroll
    for (int i = 0; i < 8; i++)
#pragma unroll
        for (int j = 0; j < 8; j++) acc[i][j] = 0.0f;

    // prefetch first tile into registers
    float4 pa0 = *(const float4*)(A + arow0 + lk);
    float4 pa1 = *(const float4*)(A + arow1 + lk);
    float4 pw0 = *(const float4*)(W0 + lk);
    float4 pw1 = *(const float4*)(W1 + lk);

    for (int k0 = 0; k0 < K; k0 += 16) {
        // stage prefetched tile (transposed: [k][m])
        As[(lk + 0) * 132 + lrow] = pa0.x;
        As[(lk + 1) * 132 + lrow] = pa0.y;
        As[(lk + 2) * 132 + lrow] = pa0.z;
        As[(lk + 3) * 132 + lrow] = pa0.w;
        As[(lk + 0) * 132 + lrow + 64] = pa1.x;
        As[(lk + 1) * 132 + lrow + 64] = pa1.y;
        As[(lk + 2) * 132 + lrow + 64] = pa1.z;
        As[(lk + 3) * 132 + lrow + 64] = pa1.w;
        Bs[(lk + 0) * 132 + lrow] = pw0.x;
        Bs[(lk + 1) * 132 + lrow] = pw0.y;
        Bs[(lk + 2) * 132 + lrow] = pw0.z;
        Bs[(lk + 3) * 132 + lrow] = pw0.w;
        Bs[(lk + 0) * 132 + lrow + 64] = pw1.x;
        Bs[(lk + 1) * 132 + lrow + 64] = pw1.y;
        Bs[(lk + 2) * 132 + lrow + 64] = pw1.z;
        Bs[(lk + 3) * 132 + lrow + 64] = pw1.w;
        __syncthreads();

        if (k0 + 16 < K) {  // prefetch next tile while computing
            pa0 = *(const float4*)(A + arow0 + k0 + 16 + lk);
            pa1 = *(const float4*)(A + arow1 + k0 + 16 + lk);
            pw0 = *(const float4*)(W0 + k0 + 16 + lk);
            pw1 = *(const float4*)(W1 + k0 + 16 + lk);
        }

#pragma unroll
        for (int kk = 0; kk < 16; kk++) {
            float a[8], b[8];
            *(float4*)&a[0] = *(const float4*)&As[kk * 132 + ty * 8];
            *(float4*)&a[4] = *(const float4*)&As[kk * 132 + ty * 8 + 4];
            *(float4*)&b[0] = *(const float4*)&Bs[kk * 132 + tx * 8];
            *(float4*)&b[4] = *(const float4*)&Bs[kk * 132 + tx * 8 + 4];
#pragma unroll
            for (int i = 0; i < 8; i++)
#pragma unroll
                for (int j = 0; j < 8; j++) acc[i][j] += a[i] * b[j];
        }
        __syncthreads();
    }

    // epilogue: bias + store
    float bcol[8];
#pragma unroll
    for (int j = 0; j < 8; j++) {
        int n = bn + tx * 8 + j;
        float v = b1[n];
        if (b2) v += b2[n];
        bcol[j] = v;
    }
#pragma unroll
    for (int i = 0; i < 8; i++) {
        int m = bm + ty * 8 + i;
        size_t crow = cmode ? ((size_t)(m & 31) * Tlen + (size_t)(m >> 5)) * (size_t)N
                            : (size_t)m * N;
        int n0 = bn + tx * 8;
        float4 v0, v1;
        v0.x = acc[i][0] + bcol[0]; v0.y = acc[i][1] + bcol[1];
        v0.z = acc[i][2] + bcol[2]; v0.w = acc[i][3] + bcol[3];
        v1.x = acc[i][4] + bcol[4]; v1.y = acc[i][5] + bcol[5];
        v1.z = acc[i][6] + bcol[6]; v1.w = acc[i][7] + bcol[7];
        *(float4*)&C[crow + n0]     = v0;
        *(float4*)&C[crow + n0 + 4] = v1;
    }
}

// ---------------- persistent recurrent kernel --------------------------------
// 128 CTAs, CTA c owns h-dims d0=4c..4c+3 (16 gate rows: j = gate*4+dd).
// Per step: gates = G[t] + h(t-1) @ Wh^T for owned rows, activations, c update,
// publish h chunk to g_hkb[t][k][b] and hseq[t*B+b][d].
__global__ __launch_bounds__(RTHREADS) void lstm_rec(
    const float* __restrict__ G, const float* __restrict__ Wh,
    float* __restrict__ hkb, float* __restrict__ hseq,
    int* __restrict__ cnt)
{
    extern __shared__ float sm[];
    float* Wsh = sm;                        // [512][16]  j-contiguous
    float* hsh = sm + 8192;                 // [512][32]  b-contiguous
    float* red = hsh + 16384;               // [8][512]   partials per k-warp
    float* csh = red + 4096;                // [128]      cell state (dd*32+b)

    const int tid = threadIdx.x;
    const int c   = blockIdx.x;
    const int d0  = c * 4;

    // stage recurrent weights once: Wsh[k*16 + j] = Wh[gate*H + d0+dd][k]
#pragma unroll
    for (int j = 0; j < 16; j++) {
        int gate = j >> 2, dd = j & 3;
        const float* src = Wh + ((size_t)gate * Hdim + d0 + dd) * Hdim;
        for (int k = tid; k < Hdim; k += RTHREADS) Wsh[k * 16 + j] = src[k];
    }
    if (tid < 128) csh[tid] = 0.0f;
    __syncthreads();

    const int kk = tid >> 5;          // k-chunk (warp) 0..7
    const int bb = (tid >> 2) & 7;    // b-group 0..7
    const int jj = tid & 3;           // gate group 0..3 (i,f,g,o)

    for (int t = 0; t < Tlen; t++) {
        if (t > 0) {
            if (tid == 0) {  // wait for full h(t-1)
                volatile int* vc = cnt;
                while (vc[t - 1] < NCTA) {}
            }
            __syncthreads();
            // load h(t-1) into smem (L2-only loads)
            const float4* src = (const float4*)(hkb + (size_t)(t - 1) * Hdim * Bsz);
            float4* dst = (float4*)hsh;
#pragma unroll 4
            for (int i = tid; i < (Hdim * Bsz) / 4; i += RTHREADS) dst[i] = __ldcg(src + i);
            __syncthreads();

            float4 a0 = {0, 0, 0, 0}, a1 = a0, a2 = a0, a3 = a0;
            const float* wp = Wsh + jj * 4 + kk * 64 * 16;
            const float* hp = hsh + bb * 4 + kk * 64 * 32;
#pragma unroll 8
            for (int kr = 0; kr < 64; kr++) {
                float4 wv = *(const float4*)(wp + kr * 16);
                float4 hv = *(const float4*)(hp + kr * 32);
                a0.x += wv.x * hv.x; a0.y += wv.x * hv.y; a0.z += wv.x * hv.z; a0.w += wv.x * hv.w;
                a1.x += wv.y * hv.x; a1.y += wv.y * hv.y; a1.z += wv.y * hv.z; a1.w += wv.y * hv.w;
                a2.x += wv.z * hv.x; a2.y += wv.z * hv.y; a2.z += wv.z * hv.z; a2.w += wv.z * hv.w;
                a3.x += wv.w * hv.x; a3.y += wv.w * hv.y; a3.z += wv.w * hv.z; a3.w += wv.w * hv.w;
            }
            float* rp = red + kk * 512 + bb * 4;
            *(float4*)(rp + (jj * 4 + 0) * 32) = a0;
            *(float4*)(rp + (jj * 4 + 1) * 32) = a1;
            *(float4*)(rp + (jj * 4 + 2) * 32) = a2;
            *(float4*)(rp + (jj * 4 + 3) * 32) = a3;
        }
        __syncthreads();

        if (tid < 128) {
            int dd = tid >> 5, b = tid & 31;
            const float* gbase = G + ((size_t)t * Bsz + b) * G4 + d0 + dd;
            float s[4];
#pragma unroll
            for (int gate = 0; gate < 4; gate++) {
                float v = __ldg(gbase + gate * Hdim);
                if (t > 0) {
                    int o = (gate * 4 + dd) * 32 + b;
#pragma unroll
                    for (int w = 0; w < 8; w++) v += red[w * 512 + o];
                }
                s[gate] = v;
            }
            float ig = sigm_(s[0]);
            float fg = sigm_(s[1]);
            float gg = tanh_(s[2]);
            float og = sigm_(s[3]);
            float cv = fg * csh[tid] + ig * gg;
            csh[tid] = cv;
            float hv = og * tanh_(cv);
            hkb[(size_t)t * Hdim * Bsz + (size_t)(d0 + dd) * Bsz + b] = hv;
            hseq[((size_t)t * Bsz + b) * Hdim + d0 + dd] = hv;
        }
        __threadfence();
        __syncthreads();
        if (tid == 0) atomicAdd(&cnt[t], 1);
    }
}

// ---------------- launcher ---------------------------------------------------
extern "C" void kernel_launch(void* const* d_in, const int* in_sizes, int n_in,
                              void* d_out, int out_size)
{
    (void)in_sizes; (void)n_in; (void)out_size;
    const float* x     = (const float*)d_in[0];
    const float* W_ih  = (const float*)d_in[1];   // [2][2048][512]
    const float* W_hh  = (const float*)d_in[2];   // [2][2048][512]
    const float* b_ih  = (const float*)d_in[3];   // [2][2048]
    const float* b_hh  = (const float*)d_in[4];   // [2][2048]
    const float* W_out = (const float*)d_in[5];   // [512][512]
    const float* b_out = (const float*)d_in[6];   // [512]
    float* out = (float*)d_out;

    float *G, *h1, *h2, *hkb; int* cnt;
    cudaGetSymbolAddress((void**)&G,   g_G);
    cudaGetSymbolAddress((void**)&h1,  g_h1);
    cudaGetSymbolAddress((void**)&h2,  g_h2);
    cudaGetSymbolAddress((void**)&hkb, g_hkb);
    cudaGetSymbolAddress((void**)&cnt, g_cnt);

    const int rec_smem = (8192 + 16384 + 4096 + 128) * 4;  // 115200 B
    cudaFuncSetAttribute(lstm_rec, cudaFuncAttributeMaxDynamicSharedMemorySize, rec_smem);

    zero_cnt_kernel<<<8, 256>>>();

    // layer 0
    sgemm_nt<<<dim3(G4 / 128, Mrows / 128), 256>>>(
        x, W_ih, b_ih, b_hh, G, G4, /*amode=*/0, /*cmode=*/0);
    lstm_rec<<<NCTA, RTHREADS, rec_smem>>>(G, W_hh, hkb, h1, cnt);

    // layer 1
    const size_t wl = (size_t)G4 * Hdim;  // per-layer weight stride
    sgemm_nt<<<dim3(G4 / 128, Mrows / 128), 256>>>(
        h1, W_ih + wl, b_ih + G4, b_hh + G4, G, G4, /*amode=*/1, /*cmode=*/0);
    lstm_rec<<<NCTA, RTHREADS, rec_smem>>>(G, W_hh + wl, hkb, h2, cnt + Tlen);

    // output projection -> [B,T,H]
    sgemm_nt<<<dim3(Hdim / 128, Mrows / 128), 256>>>(
        h2, W_out, b_out, nullptr, out, Hdim, /*amode=*/1, /*cmode=*/1);
}

// round 7
// speedup vs baseline: 1.1669x; 1.1669x over previous
#include <cuda_runtime.h>
#include <cstdint>
#include <cstddef>

// Problem constants
#define Bsz   32
#define Tlen  1024
#define Hdim  512
#define G4    2048                 // 4*H
#define Mrows (Tlen * Bsz)         // 32768
#define NCTA  128                  // recurrent CTAs
#define RTHREADS 256

// ---------------- static device scratch (no allocations allowed) -------------
__device__ float g_G[(size_t)Mrows * G4];          // gate pre-activations [t*B+b][4H]
__device__ float g_h1[(size_t)Mrows * Hdim];       // layer-0 outputs [t*B+b][H]
__device__ float g_h2[(size_t)Mrows * Hdim];       // layer-1 outputs [t*B+b][H]
__device__ float g_hkb[(size_t)Tlen * Hdim * Bsz]; // h in [t][k][b] layout
__device__ int   g_cnt[2][Tlen];                   // per-step arrival counters

// ---------------- helpers ----------------------------------------------------
__device__ __forceinline__ float sigm_(float x) { return 1.0f / (1.0f + __expf(-x)); }
__device__ __forceinline__ float tanh_(float x) {
    float y;
    asm("tanh.approx.f32 %0, %1;" : "=f"(y) : "f"(x));
    return y;
}
__device__ __forceinline__ uint32_t f2tf32(float x) {
    uint32_t r;
    asm("cvt.rna.tf32.f32 %0, %1;" : "=r"(r) : "f"(x));
    return r;
}
__device__ __forceinline__ void mma_tf32(float* c, const uint32_t* a, const uint32_t* b) {
    asm volatile("mma.sync.aligned.m16n8k8.row.col.f32.tf32.tf32.f32 "
                 "{%0,%1,%2,%3}, {%4,%5,%6,%7}, {%8,%9}, {%0,%1,%2,%3};"
                 : "+f"(c[0]), "+f"(c[1]), "+f"(c[2]), "+f"(c[3])
                 : "r"(a[0]), "r"(a[1]), "r"(a[2]), "r"(a[3]), "r"(b[0]), "r"(b[1]));
}

// ---------------- counter reset (graph-replay safe) --------------------------
__global__ void zero_cnt_kernel() {
    int i = blockIdx.x * blockDim.x + threadIdx.x;
    if (i < 2 * Tlen) ((int*)g_cnt)[i] = 0;
}

// =============================================================================
// tf32 mma.sync 3-pass split GEMM:  C[m][n] = sum_k A[m][k]*W[n][k] + bias
// hi = tf32(x), mid = tf32(x - hi); C = Ahi*Whi + Ahi*Wmid + Amid*Whi.
// CTA tile 128x128, K staged 32/iter (raw fp32 in smem), 8 warps (4M x 2N),
// warp tile 32x64. No ldmatrix: fragments gathered with plain shared loads
// (row stride 36 floats => stride mod 32 = 4 => conflict-free lane->bank map).
// amode 0: A row m -> x[(m&31)*T + (m>>5)]   (x is [B,T,H])
// amode 1: A row m -> A[m]
// cmode 0: C row m -> C[m*Ntot]
// cmode 1: C row m -> C[((m&31)*T + (m>>5))*Ntot]
// =============================================================================
#define TM 128
#define TN 128
#define KS 32
#define RST 36                     // smem row stride in floats (144 B)
#define MAT_F (128 * RST)          // 4608 floats per tile
#define BUF_F (2 * MAT_F)          // A tile + W tile, floats
#define OFF_A 0
#define OFF_W MAT_F
#define BUF_BYTES (BUF_F * 4)      // 36864 B per stage buffer

__global__ __launch_bounds__(256, 1) void gemm_tf32(
    const float* __restrict__ A, const float* __restrict__ W,
    const float* __restrict__ b1, const float* __restrict__ b2,
    float* __restrict__ C, int Ntot, int amode, int cmode)
{
    extern __shared__ float smf[];

    const int tid  = threadIdx.x;
    const int wid  = tid >> 5;
    const int lane = tid & 31;
    const int bm = blockIdx.y * TM;
    const int bn = blockIdx.x * TN;
    const int wm = (wid & 3) * 32;     // warp M offset
    const int wn = (wid >> 2) * 64;    // warp N offset
    const int g  = lane >> 2;          // fragment row group 0..7
    const int cfrag = lane & 3;        // fragment col 0..3

    // ---- staging assignment: thread covers row tid>>1, half (tid&1)*16 -----
    const int rr  = tid >> 1;
    const int cc0 = (tid & 1) * 16;
    size_t arow;
    {
        int m = bm + rr;
        arow = amode ? (size_t)m * Hdim
                     : ((size_t)(m & 31) * Tlen + (size_t)(m >> 5)) * Hdim;
    }
    const float* ap = A + arow;
    const float* wp = W + (size_t)(bn + rr) * Hdim;
    const int sts = rr * RST + cc0;    // float offset of this thread's stage slot

    float acc[2][8][4];
#pragma unroll
    for (int i = 0; i < 2; i++)
#pragma unroll
        for (int j = 0; j < 8; j++)
#pragma unroll
            for (int q = 0; q < 4; q++) acc[i][j][q] = 0.0f;

    // prefetch stage 0 into registers
    float4 pa[4], pw[4];
#pragma unroll
    for (int i = 0; i < 4; i++) {
        pa[i] = __ldg((const float4*)(ap + cc0 + i * 4));
        pw[i] = __ldg((const float4*)(wp + cc0 + i * 4));
    }

    const int NSTG = Hdim / KS;  // 16
    for (int kt = 0; kt < NSTG; kt++) {
        float* buf = smf + (kt & 1) * BUF_F;
        // ---- stage raw fp32 tiles ----
#pragma unroll
        for (int i = 0; i < 4; i++) {
            *(float4*)&buf[OFF_A + sts + i * 4] = pa[i];
            *(float4*)&buf[OFF_W + sts + i * 4] = pw[i];
        }
        __syncthreads();

        if (kt + 1 < NSTG) {  // prefetch next stage
            int kb = (kt + 1) * KS + cc0;
#pragma unroll
            for (int i = 0; i < 4; i++) {
                pa[i] = __ldg((const float4*)(ap + kb + i * 4));
                pw[i] = __ldg((const float4*)(wp + kb + i * 4));
            }
        }

        const float* As = buf + OFF_A;
        const float* Ws = buf + OFF_W;
        // ---- compute: 4 x K8 steps ----
#pragma unroll
        for (int ks = 0; ks < 4; ks++) {
            const int kof = ks * 8 + cfrag;
            // A fragments (hi/mid) for j = 0,1
            uint32_t ah[2][4], am[2][4];
#pragma unroll
            for (int j = 0; j < 2; j++) {
                int ra = (wm + j * 16 + g) * RST + kof;
                float v0 = As[ra];
                float v1 = As[ra + 8 * RST];
                float v2 = As[ra + 4];
                float v3 = As[ra + 8 * RST + 4];
                ah[j][0] = f2tf32(v0); am[j][0] = f2tf32(v0 - __uint_as_float(ah[j][0]));
                ah[j][1] = f2tf32(v1); am[j][1] = f2tf32(v1 - __uint_as_float(ah[j][1]));
                ah[j][2] = f2tf32(v2); am[j][2] = f2tf32(v2 - __uint_as_float(ah[j][2]));
                ah[j][3] = f2tf32(v3); am[j][3] = f2tf32(v3 - __uint_as_float(ah[j][3]));
            }
            // B fragments (hi/mid) for n = 0..7
            uint32_t bh[8][2], bmid[8][2];
#pragma unroll
            for (int n = 0; n < 8; n++) {
                int rb = (wn + n * 8 + g) * RST + kof;
                float v0 = Ws[rb];
                float v1 = Ws[rb + 4];
                bh[n][0] = f2tf32(v0); bmid[n][0] = f2tf32(v0 - __uint_as_float(bh[n][0]));
                bh[n][1] = f2tf32(v1); bmid[n][1] = f2tf32(v1 - __uint_as_float(bh[n][1]));
            }
#pragma unroll
            for (int j = 0; j < 2; j++)
#pragma unroll
                for (int n = 0; n < 8; n++) {
                    mma_tf32(acc[j][n], ah[j], bh[n]);    // hi*hi
                    mma_tf32(acc[j][n], ah[j], bmid[n]);  // hi*mid
                    mma_tf32(acc[j][n], am[j], bh[n]);    // mid*hi
                }
        }
        __syncthreads();
    }

    // ---- epilogue: bias + store (C frag: row g (+8), col 2*cfrag (+1)) ----
    const int cr = g;
    const int cn = cfrag * 2;
#pragma unroll
    for (int n = 0; n < 8; n++) {
        int ncol = bn + wn + n * 8 + cn;
        float bx = __ldg(b1 + ncol)     + (b2 ? __ldg(b2 + ncol)     : 0.0f);
        float by = __ldg(b1 + ncol + 1) + (b2 ? __ldg(b2 + ncol + 1) : 0.0f);
#pragma unroll
        for (int j = 0; j < 2; j++) {
            int m0 = bm + wm + j * 16 + cr;
#pragma unroll
            for (int h = 0; h < 2; h++) {
                int m = m0 + h * 8;
                size_t crow = cmode
                    ? ((size_t)(m & 31) * Tlen + (size_t)(m >> 5)) * (size_t)Ntot
                    : (size_t)m * Ntot;
                float2 v;
                v.x = acc[j][n][h * 2 + 0] + bx;
                v.y = acc[j][n][h * 2 + 1] + by;
                *(float2*)&C[crow + ncol] = v;
            }
        }
    }
}

// =============================================================================
// persistent recurrent kernel (fp32). 128 CTAs; CTA c owns h-dims 4c..4c+3.
// Sync protocol identical to the round-2 PASSING kernel (tid0 volatile spin,
// __threadfence + atomicAdd publish). Only change vs round 2: G[t] prefetch.
// =============================================================================
__global__ __launch_bounds__(RTHREADS) void lstm_rec(
    const float* __restrict__ G, const float* __restrict__ Wh,
    float* __restrict__ hkb, float* __restrict__ hseq,
    int* __restrict__ cnt)
{
    extern __shared__ float sm[];
    float* Wsh = sm;                        // [512][16]  j-contiguous
    float* hsh = sm + 8192;                 // [512][32]  b-contiguous
    float* red = hsh + 16384;               // [8][512]   partials per k-warp
    float* csh = red + 4096;                // [128]      cell state (dd*32+b)

    const int tid = threadIdx.x;
    const int c   = blockIdx.x;
    const int d0  = c * 4;

    // stage recurrent weights once: Wsh[k*16 + j] = Wh[gate*H + d0+dd][k]
#pragma unroll
    for (int j = 0; j < 16; j++) {
        int gate = j >> 2, dd = j & 3;
        const float* src = Wh + ((size_t)gate * Hdim + d0 + dd) * Hdim;
        for (int k = tid; k < Hdim; k += RTHREADS) Wsh[k * 16 + j] = src[k];
    }
    if (tid < 128) csh[tid] = 0.0f;
    __syncthreads();

    const int kk = tid >> 5;          // k-chunk (warp) 0..7
    const int bb = (tid >> 2) & 7;    // b-group 0..7
    const int jj = tid & 3;           // gate group 0..3
    const int dd = tid >> 5;          // activation role (tid<128)
    const int b  = tid & 31;

    for (int t = 0; t < Tlen; t++) {
        // prefetch this step's gate pre-activations (independent of h)
        float gp0 = 0.f, gp1 = 0.f, gp2 = 0.f, gp3 = 0.f;
        if (tid < 128) {
            const float* gb = G + ((size_t)t * Bsz + b) * G4 + d0 + dd;
            gp0 = __ldg(gb);
            gp1 = __ldg(gb + Hdim);
            gp2 = __ldg(gb + 2 * Hdim);
            gp3 = __ldg(gb + 3 * Hdim);
        }
        if (t > 0) {
            if (tid == 0) {  // wait for full h(t-1)  (round-2 proven protocol)
                volatile int* vc = cnt;
                while (vc[t - 1] < NCTA) {}
            }
            __syncthreads();
            // load h(t-1) into smem (L2 broadcast, bypass L1)
            const float4* src = (const float4*)(hkb + (size_t)(t - 1) * Hdim * Bsz);
            float4* dst = (float4*)hsh;
#pragma unroll
            for (int i = 0; i < 16; i++) dst[tid + i * 256] = __ldcg(src + tid + i * 256);
            __syncthreads();

            float4 a0 = {0, 0, 0, 0}, a1 = a0, a2 = a0, a3 = a0;
            const float* wp2 = Wsh + jj * 4 + kk * 64 * 16;
            const float* hp = hsh + bb * 4 + kk * 64 * 32;
#pragma unroll 8
            for (int kr = 0; kr < 64; kr++) {
                float4 wv = *(const float4*)(wp2 + kr * 16);
                float4 hv = *(const float4*)(hp + kr * 32);
                a0.x += wv.x * hv.x; a0.y += wv.x * hv.y; a0.z += wv.x * hv.z; a0.w += wv.x * hv.w;
                a1.x += wv.y * hv.x; a1.y += wv.y * hv.y; a1.z += wv.y * hv.z; a1.w += wv.y * hv.w;
                a2.x += wv.z * hv.x; a2.y += wv.z * hv.y; a2.z += wv.z * hv.z; a2.w += wv.z * hv.w;
                a3.x += wv.w * hv.x; a3.y += wv.w * hv.y; a3.z += wv.w * hv.z; a3.w += wv.w * hv.w;
            }
            float* rp = red + kk * 512 + bb * 4;
            *(float4*)(rp + (jj * 4 + 0) * 32) = a0;
            *(float4*)(rp + (jj * 4 + 1) * 32) = a1;
            *(float4*)(rp + (jj * 4 + 2) * 32) = a2;
            *(float4*)(rp + (jj * 4 + 3) * 32) = a3;
        }
        __syncthreads();

        if (tid < 128) {
            float s0 = gp0, s1 = gp1, s2 = gp2, s3 = gp3;
            if (t > 0) {
                int o0 = (0 * 4 + dd) * 32 + b;
                int o1 = (1 * 4 + dd) * 32 + b;
                int o2 = (2 * 4 + dd) * 32 + b;
                int o3 = (3 * 4 + dd) * 32 + b;
#pragma unroll
                for (int w = 0; w < 8; w++) {
                    s0 += red[w * 512 + o0];
                    s1 += red[w * 512 + o1];
                    s2 += red[w * 512 + o2];
                    s3 += red[w * 512 + o3];
                }
            }
            float ig = sigm_(s0);
            float fg = sigm_(s1);
            float gg = tanh_(s2);
            float og = sigm_(s3);
            float cv = fg * csh[tid] + ig * gg;
            csh[tid] = cv;
            float hv = og * tanh_(cv);
            hkb[(size_t)t * Hdim * Bsz + (size_t)(d0 + dd) * Bsz + b] = hv;
            hseq[((size_t)t * Bsz + b) * Hdim + d0 + dd] = hv;
        }
        __threadfence();
        __syncthreads();
        if (tid == 0) atomicAdd(&cnt[t], 1);
    }
}

// ---------------- launcher ---------------------------------------------------
extern "C" void kernel_launch(void* const* d_in, const int* in_sizes, int n_in,
                              void* d_out, int out_size)
{
    (void)in_sizes; (void)n_in; (void)out_size;
    const float* x     = (const float*)d_in[0];
    const float* W_ih  = (const float*)d_in[1];   // [2][2048][512]
    const float* W_hh  = (const float*)d_in[2];   // [2][2048][512]
    const float* b_ih  = (const float*)d_in[3];   // [2][2048]
    const float* b_hh  = (const float*)d_in[4];   // [2][2048]
    const float* W_out = (const float*)d_in[5];   // [512][512]
    const float* b_out = (const float*)d_in[6];   // [512]
    float* out = (float*)d_out;

    float *G, *h1, *h2, *hkb; int* cnt;
    cudaGetSymbolAddress((void**)&G,   g_G);
    cudaGetSymbolAddress((void**)&h1,  g_h1);
    cudaGetSymbolAddress((void**)&h2,  g_h2);
    cudaGetSymbolAddress((void**)&hkb, g_hkb);
    cudaGetSymbolAddress((void**)&cnt, g_cnt);

    const int rec_smem  = (8192 + 16384 + 4096 + 128) * 4;  // 115200 B
    const int gemm_smem = 2 * BUF_BYTES;                    // 73728 B
    cudaFuncSetAttribute(lstm_rec, cudaFuncAttributeMaxDynamicSharedMemorySize, rec_smem);
    cudaFuncSetAttribute(gemm_tf32, cudaFuncAttributeMaxDynamicSharedMemorySize, gemm_smem);

    zero_cnt_kernel<<<8, 256>>>();

    // layer 0: gates = x @ Wih0^T + b
    gemm_tf32<<<dim3(G4 / TN, Mrows / TM), 256, gemm_smem>>>(
        x, W_ih, b_ih, b_hh, G, G4, /*amode=*/0, /*cmode=*/0);
    lstm_rec<<<NCTA, RTHREADS, rec_smem>>>(G, W_hh, hkb, h1, cnt);

    // layer 1
    const size_t wl = (size_t)G4 * Hdim;
    gemm_tf32<<<dim3(G4 / TN, Mrows / TM), 256, gemm_smem>>>(
        h1, W_ih + wl, b_ih + G4, b_hh + G4, G, G4, /*amode=*/1, /*cmode=*/0);
    lstm_rec<<<NCTA, RTHREADS, rec_smem>>>(G, W_hh + wl, hkb, h2, cnt + Tlen);

    // output projection -> [B,T,H]
    gemm_tf32<<<dim3(Hdim / TN, Mrows / TM), 256, gemm_smem>>>(
        h2, W_out, b_out, nullptr, out, Hdim, /*amode=*/1, /*cmode=*/1);
}

// round 8
// speedup vs baseline: 1.1900x; 1.0197x over previous
#include <cuda_runtime.h>
#include <cstdint>
#include <cstddef>

// Problem constants
#define Bsz   32
#define Tlen  1024
#define Hdim  512
#define G4    2048                 // 4*H
#define Mrows (Tlen * Bsz)         // 32768
#define NCTA  128                  // recurrent CTAs
#define RTHREADS 256

// ---------------- static device scratch (no allocations allowed) -------------
__device__ float g_G[(size_t)Mrows * G4];          // gate pre-activations [t*B+b][4H]
__device__ float g_h1[(size_t)Mrows * Hdim];       // layer-0 outputs [t*B+b][H]
__device__ float g_h2[(size_t)Mrows * Hdim];       // layer-1 outputs [t*B+b][H]
__device__ float g_hkb[(size_t)Tlen * Hdim * Bsz]; // h in [t][k][b] layout
__device__ int   g_cnt[2][Tlen];                   // per-step arrival counters

// ---------------- helpers ----------------------------------------------------
__device__ __forceinline__ float sigm_(float x) { return 1.0f / (1.0f + __expf(-x)); }
__device__ __forceinline__ float tanh_(float x) {
    float y;
    asm("tanh.approx.f32 %0, %1;" : "=f"(y) : "f"(x));
    return y;
}
__device__ __forceinline__ uint32_t f2tf32(float x) {
    uint32_t r;
    asm("cvt.rna.tf32.f32 %0, %1;" : "=r"(r) : "f"(x));
    return r;
}
__device__ __forceinline__ void mma_tf32(float* c, const uint32_t* a, const uint32_t* b) {
    asm volatile("mma.sync.aligned.m16n8k8.row.col.f32.tf32.tf32.f32 "
                 "{%0,%1,%2,%3}, {%4,%5,%6,%7}, {%8,%9}, {%0,%1,%2,%3};"
                 : "+f"(c[0]), "+f"(c[1]), "+f"(c[2]), "+f"(c[3])
                 : "r"(a[0]), "r"(a[1]), "r"(a[2]), "r"(a[3]), "r"(b[0]), "r"(b[1]));
}

// ---------------- counter reset (graph-replay safe) --------------------------
__global__ void zero_cnt_kernel() {
    int i = blockIdx.x * blockDim.x + threadIdx.x;
    if (i < 2 * Tlen) ((int*)g_cnt)[i] = 0;
}

// =============================================================================
// tf32 mma.sync 3-pass split GEMM (UNCHANGED from round-7 passing kernel)
// =============================================================================
#define TM 128
#define TN 128
#define KS 32
#define RST 36                     // smem row stride in floats (144 B)
#define MAT_F (128 * RST)
#define BUF_F (2 * MAT_F)
#define OFF_A 0
#define OFF_W MAT_F
#define BUF_BYTES (BUF_F * 4)      // 36864 B per stage buffer

__global__ __launch_bounds__(256, 1) void gemm_tf32(
    const float* __restrict__ A, const float* __restrict__ W,
    const float* __restrict__ b1, const float* __restrict__ b2,
    float* __restrict__ C, int Ntot, int amode, int cmode)
{
    extern __shared__ float smf[];

    const int tid  = threadIdx.x;
    const int wid  = tid >> 5;
    const int lane = tid & 31;
    const int bm = blockIdx.y * TM;
    const int bn = blockIdx.x * TN;
    const int wm = (wid & 3) * 32;
    const int wn = (wid >> 2) * 64;
    const int g  = lane >> 2;
    const int cfrag = lane & 3;

    const int rr  = tid >> 1;
    const int cc0 = (tid & 1) * 16;
    size_t arow;
    {
        int m = bm + rr;
        arow = amode ? (size_t)m * Hdim
                     : ((size_t)(m & 31) * Tlen + (size_t)(m >> 5)) * Hdim;
    }
    const float* ap = A + arow;
    const float* wp = W + (size_t)(bn + rr) * Hdim;
    const int sts = rr * RST + cc0;

    float acc[2][8][4];
#pragma unroll
    for (int i = 0; i < 2; i++)
#pragma unroll
        for (int j = 0; j < 8; j++)
#pragma unroll
            for (int q = 0; q < 4; q++) acc[i][j][q] = 0.0f;

    float4 pa[4], pw[4];
#pragma unroll
    for (int i = 0; i < 4; i++) {
        pa[i] = __ldg((const float4*)(ap + cc0 + i * 4));
        pw[i] = __ldg((const float4*)(wp + cc0 + i * 4));
    }

    const int NSTG = Hdim / KS;  // 16
    for (int kt = 0; kt < NSTG; kt++) {
        float* buf = smf + (kt & 1) * BUF_F;
#pragma unroll
        for (int i = 0; i < 4; i++) {
            *(float4*)&buf[OFF_A + sts + i * 4] = pa[i];
            *(float4*)&buf[OFF_W + sts + i * 4] = pw[i];
        }
        __syncthreads();

        if (kt + 1 < NSTG) {
            int kb = (kt + 1) * KS + cc0;
#pragma unroll
            for (int i = 0; i < 4; i++) {
                pa[i] = __ldg((const float4*)(ap + kb + i * 4));
                pw[i] = __ldg((const float4*)(wp + kb + i * 4));
            }
        }

        const float* As = buf + OFF_A;
        const float* Ws = buf + OFF_W;
#pragma unroll
        for (int ks = 0; ks < 4; ks++) {
            const int kof = ks * 8 + cfrag;
            uint32_t ah[2][4], am[2][4];
#pragma unroll
            for (int j = 0; j < 2; j++) {
                int ra = (wm + j * 16 + g) * RST + kof;
                float v0 = As[ra];
                float v1 = As[ra + 8 * RST];
                float v2 = As[ra + 4];
                float v3 = As[ra + 8 * RST + 4];
                ah[j][0] = f2tf32(v0); am[j][0] = f2tf32(v0 - __uint_as_float(ah[j][0]));
                ah[j][1] = f2tf32(v1); am[j][1] = f2tf32(v1 - __uint_as_float(ah[j][1]));
                ah[j][2] = f2tf32(v2); am[j][2] = f2tf32(v2 - __uint_as_float(ah[j][2]));
                ah[j][3] = f2tf32(v3); am[j][3] = f2tf32(v3 - __uint_as_float(ah[j][3]));
            }
            uint32_t bh[8][2], bmid[8][2];
#pragma unroll
            for (int n = 0; n < 8; n++) {
                int rb = (wn + n * 8 + g) * RST + kof;
                float v0 = Ws[rb];
                float v1 = Ws[rb + 4];
                bh[n][0] = f2tf32(v0); bmid[n][0] = f2tf32(v0 - __uint_as_float(bh[n][0]));
                bh[n][1] = f2tf32(v1); bmid[n][1] = f2tf32(v1 - __uint_as_float(bh[n][1]));
            }
#pragma unroll
            for (int j = 0; j < 2; j++)
#pragma unroll
                for (int n = 0; n < 8; n++) {
                    mma_tf32(acc[j][n], ah[j], bh[n]);
                    mma_tf32(acc[j][n], ah[j], bmid[n]);
                    mma_tf32(acc[j][n], am[j], bh[n]);
                }
        }
        __syncthreads();
    }

    const int cr = g;
    const int cn = cfrag * 2;
#pragma unroll
    for (int n = 0; n < 8; n++) {
        int ncol = bn + wn + n * 8 + cn;
        float bx = __ldg(b1 + ncol)     + (b2 ? __ldg(b2 + ncol)     : 0.0f);
        float by = __ldg(b1 + ncol + 1) + (b2 ? __ldg(b2 + ncol + 1) : 0.0f);
#pragma unroll
        for (int j = 0; j < 2; j++) {
            int m0 = bm + wm + j * 16 + cr;
#pragma unroll
            for (int h = 0; h < 2; h++) {
                int m = m0 + h * 8;
                size_t crow = cmode
                    ? ((size_t)(m & 31) * Tlen + (size_t)(m >> 5)) * (size_t)Ntot
                    : (size_t)m * Ntot;
                float2 v;
                v.x = acc[j][n][h * 2 + 0] + bx;
                v.y = acc[j][n][h * 2 + 1] + by;
                *(float2*)&C[crow + ncol] = v;
            }
        }
    }
}

// =============================================================================
// persistent recurrent kernel — tensor-core version.
// 128 CTAs; CTA c owns 16 gate rows j=0..15 (gate=j>>2, dd=j&3 -> Wh row
// gate*H + 4c + dd) x 32 batch. Per step: partial[16x32] = Wchunk @ h_chunk
// via mma.sync m16n8k8 tf32, 3-pass split (Whi*hhi + Whi*hmid + Wmid*hhi).
// W fragments live in registers (loaded once). Warp kk owns k in [64kk,64kk+64):
// it polls the counter itself, loads only its own h chunk, computes with no
// cross-warp barrier until the reduction. Fragment lane maps identical to the
// hardware-validated gemm_tf32 above.
// =============================================================================
#define RSH 40                     // hsh/red row stride in floats (160 B)

__global__ __launch_bounds__(RTHREADS) void lstm_rec_mma(
    const float* __restrict__ G, const float* __restrict__ Wh,
    float* __restrict__ hkb, float* __restrict__ hseq,
    int* __restrict__ cnt)
{
    extern __shared__ float sm[];
    float* hsh = sm;                    // [512][RSH]  h(t-1), k-major
    float* red = sm + 512 * RSH;        // [8][16*RSH] per-warp partials
    float* csh = red + 8 * 16 * RSH;    // [128] cell state (dd*32+b)

    const int tid  = threadIdx.x;
    const int lane = tid & 31;
    const int kk   = tid >> 5;          // warp = k-chunk 0..7
    const int g    = lane >> 2;         // frag row group 0..7
    const int cf   = lane & 3;          // frag col 0..3
    const int d0   = blockIdx.x * 4;

    // ---- load W fragments for this warp's k-chunk into registers (hi/mid) ---
    // A row j0=g -> Wh row (g>>2)*H + d0 + (g&3); j1=g+8 likewise.
    uint32_t wh[8][4], wmd[8][4];
    {
        const int j0 = g, j1 = g + 8;
        const float* r0 = Wh + ((size_t)(j0 >> 2) * Hdim + d0 + (j0 & 3)) * Hdim;
        const float* r1 = Wh + ((size_t)(j1 >> 2) * Hdim + d0 + (j1 & 3)) * Hdim;
#pragma unroll
        for (int s = 0; s < 8; s++) {
            int k = kk * 64 + s * 8 + cf;
            float w0 = __ldg(r0 + k);
            float w1 = __ldg(r1 + k);
            float w2 = __ldg(r0 + k + 4);
            float w3 = __ldg(r1 + k + 4);
            wh[s][0] = f2tf32(w0); wmd[s][0] = f2tf32(w0 - __uint_as_float(wh[s][0]));
            wh[s][1] = f2tf32(w1); wmd[s][1] = f2tf32(w1 - __uint_as_float(wh[s][1]));
            wh[s][2] = f2tf32(w2); wmd[s][2] = f2tf32(w2 - __uint_as_float(wh[s][2]));
            wh[s][3] = f2tf32(w3); wmd[s][3] = f2tf32(w3 - __uint_as_float(wh[s][3]));
        }
    }
    if (tid < 128) csh[tid] = 0.0f;
    __syncthreads();

    const int dd = tid >> 5;            // activation role (tid<128)
    const int b  = tid & 31;

    for (int t = 0; t < Tlen; t++) {
        // prefetch this step's gate pre-activations (independent of h)
        float gp0 = 0.f, gp1 = 0.f, gp2 = 0.f, gp3 = 0.f;
        if (tid < 128) {
            const float* gb = G + ((size_t)t * Bsz + b) * G4 + d0 + dd;
            gp0 = __ldg(gb);
            gp1 = __ldg(gb + Hdim);
            gp2 = __ldg(gb + 2 * Hdim);
            gp3 = __ldg(gb + 3 * Hdim);
        }
        if (t > 0) {
            // per-warp wait for full h(t-1)
            if (lane == 0) {
                volatile int* vc = cnt;
                while (vc[t - 1] < NCTA) {}
            }
            __syncwarp();
            asm volatile("" ::: "memory");
            // warp loads its own k-chunk of h(t-1): rows kk*64..kk*64+63
            const float4* src = (const float4*)(hkb + (size_t)(t - 1) * Hdim * Bsz
                                                + (size_t)kk * 64 * Bsz);
#pragma unroll
            for (int r = 0; r < 16; r++) {
                int f = lane + r * 32;          // float4 index 0..511 in chunk
                float4 v = __ldcg(src + f);
                int k = f >> 3, bg = f & 7;
                *(float4*)&hsh[(kk * 64 + k) * RSH + bg * 4] = v;
            }
            __syncwarp();

            // compute partial[16x32] = Wchunk @ hchunk (3-pass tf32)
            float acc[4][4];
#pragma unroll
            for (int nt = 0; nt < 4; nt++)
#pragma unroll
                for (int q = 0; q < 4; q++) acc[nt][q] = 0.0f;

#pragma unroll
            for (int s = 0; s < 8; s++) {
                const int krow = kk * 64 + s * 8;
                uint32_t hh[4][2], hm[4][2];
#pragma unroll
                for (int nt = 0; nt < 4; nt++) {
                    float v0 = hsh[(krow + cf) * RSH + nt * 8 + g];
                    float v1 = hsh[(krow + cf + 4) * RSH + nt * 8 + g];
                    hh[nt][0] = f2tf32(v0); hm[nt][0] = f2tf32(v0 - __uint_as_float(hh[nt][0]));
                    hh[nt][1] = f2tf32(v1); hm[nt][1] = f2tf32(v1 - __uint_as_float(hh[nt][1]));
                }
#pragma unroll
                for (int nt = 0; nt < 4; nt++) {
                    mma_tf32(acc[nt], wh[s], hh[nt]);   // hi*hi
                    mma_tf32(acc[nt], wh[s], hm[nt]);   // hi*mid
                    mma_tf32(acc[nt], wmd[s], hh[nt]);  // mid*hi
                }
            }
            // store partials: C frag row g/g+8, col 2cf/2cf+1 within tile nt
            float* rp = red + kk * 16 * RSH;
#pragma unroll
            for (int nt = 0; nt < 4; nt++) {
                int bcol = nt * 8 + cf * 2;
                float2 lo = { acc[nt][0], acc[nt][1] };
                float2 hi = { acc[nt][2], acc[nt][3] };
                *(float2*)&rp[g * RSH + bcol]       = lo;
                *(float2*)&rp[(g + 8) * RSH + bcol] = hi;
            }
        }
        __syncthreads();

        if (tid < 128) {
            float s0 = gp0, s1 = gp1, s2 = gp2, s3 = gp3;
            if (t > 0) {
                int o0 = (0 * 4 + dd) * RSH + b;
                int o1 = (1 * 4 + dd) * RSH + b;
                int o2 = (2 * 4 + dd) * RSH + b;
                int o3 = (3 * 4 + dd) * RSH + b;
#pragma unroll
                for (int w = 0; w < 8; w++) {
                    const float* rw = red + w * 16 * RSH;
                    s0 += rw[o0];
                    s1 += rw[o1];
                    s2 += rw[o2];
                    s3 += rw[o3];
                }
            }
            float ig = sigm_(s0);
            float fg = sigm_(s1);
            float gg = tanh_(s2);
            float og = sigm_(s3);
            float cv = fg * csh[tid] + ig * gg;
            csh[tid] = cv;
            float hv = og * tanh_(cv);
            hkb[(size_t)t * Hdim * Bsz + (size_t)(d0 + dd) * Bsz + b] = hv;
            hseq[((size_t)t * Bsz + b) * Hdim + d0 + dd] = hv;
        }
        __threadfence();
        __syncthreads();
        if (tid == 0) atomicAdd(&cnt[t], 1);
    }
}

// ---------------- launcher ---------------------------------------------------
extern "C" void kernel_launch(void* const* d_in, const int* in_sizes, int n_in,
                              void* d_out, int out_size)
{
    (void)in_sizes; (void)n_in; (void)out_size;
    const float* x     = (const float*)d_in[0];
    const float* W_ih  = (const float*)d_in[1];   // [2][2048][512]
    const float* W_hh  = (const float*)d_in[2];   // [2][2048][512]
    const float* b_ih  = (const float*)d_in[3];   // [2][2048]
    const float* b_hh  = (const float*)d_in[4];   // [2][2048]
    const float* W_out = (const float*)d_in[5];   // [512][512]
    const float* b_out = (const float*)d_in[6];   // [512]
    float* out = (float*)d_out;

    float *G, *h1, *h2, *hkb; int* cnt;
    cudaGetSymbolAddress((void**)&G,   g_G);
    cudaGetSymbolAddress((void**)&h1,  g_h1);
    cudaGetSymbolAddress((void**)&h2,  g_h2);
    cudaGetSymbolAddress((void**)&hkb, g_hkb);
    cudaGetSymbolAddress((void**)&cnt, g_cnt);

    const int rec_smem  = (512 * RSH + 8 * 16 * RSH + 128) * 4;  // 102912 B
    const int gemm_smem = 2 * BUF_BYTES;                         // 73728 B
    cudaFuncSetAttribute(lstm_rec_mma, cudaFuncAttributeMaxDynamicSharedMemorySize, rec_smem);
    cudaFuncSetAttribute(gemm_tf32, cudaFuncAttributeMaxDynamicSharedMemorySize, gemm_smem);

    zero_cnt_kernel<<<8, 256>>>();

    // layer 0: gates = x @ Wih0^T + b
    gemm_tf32<<<dim3(G4 / TN, Mrows / TM), 256, gemm_smem>>>(
        x, W_ih, b_ih, b_hh, G, G4, /*amode=*/0, /*cmode=*/0);
    lstm_rec_mma<<<NCTA, RTHREADS, rec_smem>>>(G, W_hh, hkb, h1, cnt);

    // layer 1
    const size_t wl = (size_t)G4 * Hdim;
    gemm_tf32<<<dim3(G4 / TN, Mrows / TM), 256, gemm_smem>>>(
        h1, W_ih + wl, b_ih + G4, b_hh + G4, G, G4, /*amode=*/1, /*cmode=*/0);
    lstm_rec_mma<<<NCTA, RTHREADS, rec_smem>>>(G, W_hh + wl, hkb, h2, cnt + Tlen);

    // output projection -> [B,T,H]
    gemm_tf32<<<dim3(Hdim / TN, Mrows / TM), 256, gemm_smem>>>(
        h2, W_out, b_out, nullptr, out, Hdim, /*amode=*/1, /*cmode=*/1);
}